// round 1
// baseline (speedup 1.0000x reference)
#include <cuda_runtime.h>
#include <math.h>

// Problem constants
constexpr int Bb = 32;
constexpr int Ss = 512;
constexpr int DM = 256;     // d_model = H*d_k = 256
constexpr int NH = 16;
constexpr int DH = 16;      // d_k = d_v
constexpr int Mrows = Bb * Ss;  // 16384

// Scratch (allowed: __device__ globals, no runtime allocation)
__device__ float g_q[Bb * Ss * DM];
__device__ float g_k[Bb * Ss * DM];
__device__ float g_v[Bb * Ss * DM];

// ---------------------------------------------------------------------------
// Projection GEMM: C[m][n] = sum_k A[m][k] * W[n][k] + bias[n]
// M=16384, N=256, K=256.  BM=128, BN=128, BK=8, 8x8 microtile, 256 threads.
// grid = (N/BN=2, M/BM=128, 3) ; z selects which projection.
// ---------------------------------------------------------------------------
#define BM 128
#define BN 128
#define BKq 8
#define TM 8
#define TN 8

__global__ __launch_bounds__(256) void proj_gemm(
    const float* __restrict__ Qin, const float* __restrict__ Kin, const float* __restrict__ Vin,
    const float* __restrict__ WQ,  const float* __restrict__ WK,  const float* __restrict__ WV,
    const float* __restrict__ bQ,  const float* __restrict__ bK,  const float* __restrict__ bV)
{
    const float* A; const float* W; const float* bias; float* C;
    if (blockIdx.z == 0)      { A = Qin; W = WQ; bias = bQ; C = g_q; }
    else if (blockIdx.z == 1) { A = Kin; W = WK; bias = bK; C = g_k; }
    else                      { A = Vin; W = WV; bias = bV; C = g_v; }

    __shared__ float As[BKq][BM];
    __shared__ float Bs[BKq][BN];

    const int K = DM, N = DM;
    const int tid = threadIdx.x;
    const int tx = tid & 15;        // 0..15 (column microtile)
    const int ty = tid >> 4;        // 0..15 (row microtile)
    const int row0 = blockIdx.y * BM;
    const int col0 = blockIdx.x * BN;

    // load assignments: 1024 floats per tile = 256 float4, one per thread
    const int lRow = tid >> 1;          // 0..127
    const int lCol = (tid & 1) * 4;     // 0 or 4

    float acc[TM][TN];
    #pragma unroll
    for (int i = 0; i < TM; i++)
        #pragma unroll
        for (int j = 0; j < TN; j++) acc[i][j] = 0.0f;

    for (int kt = 0; kt < K; kt += BKq) {
        float4 a = *reinterpret_cast<const float4*>(A + (size_t)(row0 + lRow) * K + kt + lCol);
        As[lCol + 0][lRow] = a.x; As[lCol + 1][lRow] = a.y;
        As[lCol + 2][lRow] = a.z; As[lCol + 3][lRow] = a.w;
        float4 w = *reinterpret_cast<const float4*>(W + (size_t)(col0 + lRow) * K + kt + lCol);
        Bs[lCol + 0][lRow] = w.x; Bs[lCol + 1][lRow] = w.y;
        Bs[lCol + 2][lRow] = w.z; Bs[lCol + 3][lRow] = w.w;
        __syncthreads();

        #pragma unroll
        for (int k = 0; k < BKq; k++) {
            float4 m0 = *reinterpret_cast<const float4*>(&As[k][ty * TM]);
            float4 m1 = *reinterpret_cast<const float4*>(&As[k][ty * TM + 4]);
            float4 n0 = *reinterpret_cast<const float4*>(&Bs[k][tx * TN]);
            float4 n1 = *reinterpret_cast<const float4*>(&Bs[k][tx * TN + 4]);
            float rm[8] = {m0.x, m0.y, m0.z, m0.w, m1.x, m1.y, m1.z, m1.w};
            float rn[8] = {n0.x, n0.y, n0.z, n0.w, n1.x, n1.y, n1.z, n1.w};
            #pragma unroll
            for (int i = 0; i < TM; i++)
                #pragma unroll
                for (int j = 0; j < TN; j++)
                    acc[i][j] += rm[i] * rn[j];
        }
        __syncthreads();
    }

    // epilogue: add bias, store float4
    float bj[TN];
    #pragma unroll
    for (int j = 0; j < TN; j++) bj[j] = bias[col0 + tx * TN + j];

    #pragma unroll
    for (int i = 0; i < TM; i++) {
        float* crow = C + (size_t)(row0 + ty * TM + i) * N + col0 + tx * TN;
        float4 c0 = make_float4(acc[i][0] + bj[0], acc[i][1] + bj[1],
                                acc[i][2] + bj[2], acc[i][3] + bj[3]);
        float4 c1 = make_float4(acc[i][4] + bj[4], acc[i][5] + bj[5],
                                acc[i][6] + bj[6], acc[i][7] + bj[7]);
        *reinterpret_cast<float4*>(crow)     = c0;
        *reinterpret_cast<float4*>(crow + 4) = c1;
    }
}

// ---------------------------------------------------------------------------
// Attention: one block per (b, h); 512 threads, one q-row per thread.
// Single pass (reference uses raw exp, no max-subtraction), key-tiled so the
// K/V head-slices live in static SMEM. p = exp(q.k/4)*mask[k]; out = sum p*v / (sum p + 1e-8)
// ---------------------------------------------------------------------------
constexpr int KTILE = 256;

__global__ __launch_bounds__(512, 2) void attn_kernel(
    const float* __restrict__ mask, float* __restrict__ out)
{
    __shared__ float4 ks[KTILE][4];   // 16 KB
    __shared__ float4 vs[KTILE][4];   // 16 KB
    __shared__ float  ms[KTILE];      // 1 KB

    const int bh = blockIdx.x;
    const int b = bh >> 4;
    const int h = bh & 15;
    const int s = threadIdx.x;

    const float* qrow = g_q + ((size_t)(b * Ss + s)) * DM + h * DH;
    const float4 q0 = *reinterpret_cast<const float4*>(qrow + 0);
    const float4 q1 = *reinterpret_cast<const float4*>(qrow + 4);
    const float4 q2 = *reinterpret_cast<const float4*>(qrow + 8);
    const float4 q3 = *reinterpret_cast<const float4*>(qrow + 12);

    float4 a0 = make_float4(0.f, 0.f, 0.f, 0.f);
    float4 a1 = a0, a2 = a0, a3 = a0;
    float denom = 0.f;

    for (int t0 = 0; t0 < Ss; t0 += KTILE) {
        // cooperative load: KTILE keys * 4 float4 each for k and v
        #pragma unroll
        for (int i = threadIdx.x; i < KTILE * 4; i += 512) {
            const int key = i >> 2;
            const int c = i & 3;
            const size_t base = ((size_t)(b * Ss + t0 + key)) * DM + h * DH;
            ks[key][c] = *(reinterpret_cast<const float4*>(g_k + base) + c);
            vs[key][c] = *(reinterpret_cast<const float4*>(g_v + base) + c);
        }
        if (threadIdx.x < KTILE)
            ms[threadIdx.x] = mask[b * Ss + t0 + threadIdx.x];
        __syncthreads();

        #pragma unroll 2
        for (int key = 0; key < KTILE; key++) {
            const float4 k0 = ks[key][0], k1 = ks[key][1], k2 = ks[key][2], k3 = ks[key][3];
            float dot = q0.x * k0.x + q0.y * k0.y + q0.z * k0.z + q0.w * k0.w;
            dot += q1.x * k1.x + q1.y * k1.y + q1.z * k1.z + q1.w * k1.w;
            dot += q2.x * k2.x + q2.y * k2.y + q2.z * k2.z + q2.w * k2.w;
            dot += q3.x * k3.x + q3.y * k3.y + q3.z * k3.z + q3.w * k3.w;
            const float p = __expf(dot * 0.25f) * ms[key];
            denom += p;
            const float4 v0 = vs[key][0], v1 = vs[key][1], v2 = vs[key][2], v3 = vs[key][3];
            a0.x += p * v0.x; a0.y += p * v0.y; a0.z += p * v0.z; a0.w += p * v0.w;
            a1.x += p * v1.x; a1.y += p * v1.y; a1.z += p * v1.z; a1.w += p * v1.w;
            a2.x += p * v2.x; a2.y += p * v2.y; a2.z += p * v2.z; a2.w += p * v2.w;
            a3.x += p * v3.x; a3.y += p * v3.y; a3.z += p * v3.z; a3.w += p * v3.w;
        }
        __syncthreads();
    }

    const float inv = 1.0f / (denom + 1e-8f);
    float* orow = out + ((size_t)(b * Ss + s)) * DM + h * DH;
    *reinterpret_cast<float4*>(orow + 0)  = make_float4(a0.x * inv, a0.y * inv, a0.z * inv, a0.w * inv);
    *reinterpret_cast<float4*>(orow + 4)  = make_float4(a1.x * inv, a1.y * inv, a1.z * inv, a1.w * inv);
    *reinterpret_cast<float4*>(orow + 8)  = make_float4(a2.x * inv, a2.y * inv, a2.z * inv, a2.w * inv);
    *reinterpret_cast<float4*>(orow + 12) = make_float4(a3.x * inv, a3.y * inv, a3.z * inv, a3.w * inv);
}

// ---------------------------------------------------------------------------
extern "C" void kernel_launch(void* const* d_in, const int* in_sizes, int n_in,
                              void* d_out, int out_size)
{
    const float* Q    = (const float*)d_in[0];
    const float* K    = (const float*)d_in[1];
    const float* V    = (const float*)d_in[2];
    const float* mask = (const float*)d_in[3];
    const float* W_Q  = (const float*)d_in[4];
    const float* b_Q  = (const float*)d_in[5];
    const float* W_K  = (const float*)d_in[6];
    const float* b_K  = (const float*)d_in[7];
    const float* W_V  = (const float*)d_in[8];
    const float* b_V  = (const float*)d_in[9];
    float* out = (float*)d_out;

    // 3 projection GEMMs in one launch (z selects Q/K/V)
    dim3 gridP(DM / BN, Mrows / BM, 3);   // (2, 128, 3)
    proj_gemm<<<gridP, 256>>>(Q, K, V, W_Q, W_K, W_V, b_Q, b_K, b_V);

    // attention: one block per (b, h)
    attn_kernel<<<Bb * NH, 512>>>(mask, out);
}

// round 3
// speedup vs baseline: 1.2447x; 1.2447x over previous
#include <cuda_runtime.h>
#include <cuda_bf16.h>
#include <stdint.h>
#include <math.h>

// Problem constants
constexpr int Bb = 32;
constexpr int Ss = 512;
constexpr int DM = 256;     // d_model = H*d_k
constexpr int NH = 16;
constexpr int DH = 16;
constexpr int Mrows = Bb * Ss;  // 16384

// Scratch: split-bf16 projected q/k/v (hi + lo halves), layout [b*S+s][h*16+d]
__device__ __nv_bfloat16 g_qh[Mrows * DM], g_ql[Mrows * DM];
__device__ __nv_bfloat16 g_kh[Mrows * DM], g_kl[Mrows * DM];
__device__ __nv_bfloat16 g_vh[Mrows * DM], g_vl[Mrows * DM];

// split fp32 pair -> packed bf16 hi (return) + packed bf16 lo (out-param); a in low half
__device__ __forceinline__ uint32_t bfsplit_pack(float a, float b, uint32_t& lopack) {
    __nv_bfloat16 ah = __float2bfloat16(a), bh = __float2bfloat16(b);
    __nv_bfloat16 al = __float2bfloat16(a - __bfloat162float(ah));
    __nv_bfloat16 bl = __float2bfloat16(b - __bfloat162float(bh));
    lopack = (uint32_t)__bfloat16_as_ushort(al) | ((uint32_t)__bfloat16_as_ushort(bl) << 16);
    return (uint32_t)__bfloat16_as_ushort(ah) | ((uint32_t)__bfloat16_as_ushort(bh) << 16);
}

// m16n8k16 row.col bf16 MMA, fp32 accumulate in place
__device__ __forceinline__ void mma_bf16(float c[4],
                                         uint32_t a0, uint32_t a1, uint32_t a2, uint32_t a3,
                                         uint32_t b0, uint32_t b1) {
    asm volatile(
        "mma.sync.aligned.m16n8k16.row.col.f32.bf16.bf16.f32 "
        "{%0,%1,%2,%3}, {%4,%5,%6,%7}, {%8,%9}, {%0,%1,%2,%3};\n"
        : "+f"(c[0]), "+f"(c[1]), "+f"(c[2]), "+f"(c[3])
        : "r"(a0), "r"(a1), "r"(a2), "r"(a3), "r"(b0), "r"(b1));
}

// ===========================================================================
// Projection GEMM (fp32 compute — at scalar roofline); epilogue writes
// split-bf16 hi/lo outputs for the attention stage.
// ===========================================================================
#define BM 128
#define BN 128
#define BKq 8
#define TM 8
#define TN 8

__global__ __launch_bounds__(256) void proj_gemm(
    const float* __restrict__ Qin, const float* __restrict__ Kin, const float* __restrict__ Vin,
    const float* __restrict__ WQ,  const float* __restrict__ WK,  const float* __restrict__ WV,
    const float* __restrict__ bQ,  const float* __restrict__ bK,  const float* __restrict__ bV)
{
    const float* A; const float* W; const float* bias;
    __nv_bfloat16 *Ch, *Cl;
    if (blockIdx.z == 0)      { A = Qin; W = WQ; bias = bQ; Ch = g_qh; Cl = g_ql; }
    else if (blockIdx.z == 1) { A = Kin; W = WK; bias = bK; Ch = g_kh; Cl = g_kl; }
    else                      { A = Vin; W = WV; bias = bV; Ch = g_vh; Cl = g_vl; }

    __shared__ float As[BKq][BM];
    __shared__ float Bs[BKq][BN];

    const int K = DM, N = DM;
    const int tid = threadIdx.x;
    const int tx = tid & 15;
    const int ty = tid >> 4;
    const int row0 = blockIdx.y * BM;
    const int col0 = blockIdx.x * BN;
    const int lRow = tid >> 1;
    const int lCol = (tid & 1) * 4;

    float acc[TM][TN];
    #pragma unroll
    for (int i = 0; i < TM; i++)
        #pragma unroll
        for (int j = 0; j < TN; j++) acc[i][j] = 0.0f;

    for (int kt = 0; kt < K; kt += BKq) {
        float4 a = *reinterpret_cast<const float4*>(A + (size_t)(row0 + lRow) * K + kt + lCol);
        As[lCol + 0][lRow] = a.x; As[lCol + 1][lRow] = a.y;
        As[lCol + 2][lRow] = a.z; As[lCol + 3][lRow] = a.w;
        float4 w = *reinterpret_cast<const float4*>(W + (size_t)(col0 + lRow) * K + kt + lCol);
        Bs[lCol + 0][lRow] = w.x; Bs[lCol + 1][lRow] = w.y;
        Bs[lCol + 2][lRow] = w.z; Bs[lCol + 3][lRow] = w.w;
        __syncthreads();

        #pragma unroll
        for (int k = 0; k < BKq; k++) {
            float4 m0 = *reinterpret_cast<const float4*>(&As[k][ty * TM]);
            float4 m1 = *reinterpret_cast<const float4*>(&As[k][ty * TM + 4]);
            float4 n0 = *reinterpret_cast<const float4*>(&Bs[k][tx * TN]);
            float4 n1 = *reinterpret_cast<const float4*>(&Bs[k][tx * TN + 4]);
            float rm[8] = {m0.x, m0.y, m0.z, m0.w, m1.x, m1.y, m1.z, m1.w};
            float rn[8] = {n0.x, n0.y, n0.z, n0.w, n1.x, n1.y, n1.z, n1.w};
            #pragma unroll
            for (int i = 0; i < TM; i++)
                #pragma unroll
                for (int j = 0; j < TN; j++)
                    acc[i][j] += rm[i] * rn[j];
        }
        __syncthreads();
    }

    float bj[TN];
    #pragma unroll
    for (int j = 0; j < TN; j++) bj[j] = bias[col0 + tx * TN + j];

    #pragma unroll
    for (int i = 0; i < TM; i++) {
        const size_t off = (size_t)(row0 + ty * TM + i) * N + col0 + tx * TN;
        uint4 hi, lo;
        float v0 = acc[i][0] + bj[0], v1 = acc[i][1] + bj[1];
        float v2 = acc[i][2] + bj[2], v3 = acc[i][3] + bj[3];
        float v4 = acc[i][4] + bj[4], v5 = acc[i][5] + bj[5];
        float v6 = acc[i][6] + bj[6], v7 = acc[i][7] + bj[7];
        hi.x = bfsplit_pack(v0, v1, lo.x);
        hi.y = bfsplit_pack(v2, v3, lo.y);
        hi.z = bfsplit_pack(v4, v5, lo.z);
        hi.w = bfsplit_pack(v6, v7, lo.w);
        *reinterpret_cast<uint4*>(Ch + off) = hi;
        *reinterpret_cast<uint4*>(Cl + off) = lo;
    }
}

// ===========================================================================
// Attention via mma.sync (HMMA), register-resident flash-style.
// CTA = (q-tile 128, head, batch); 8 warps x 16 q-rows; 4 key chunks of 128.
// ===========================================================================
__global__ __launch_bounds__(256) void attn_mma(const float* __restrict__ mask,
                                                float* __restrict__ out)
{
    __shared__ __align__(16) uint32_t Qh[128 * 8], Ql[128 * 8];   // [qrow][8 u32] (16 bf16)
    __shared__ __align__(16) uint32_t Kh[128 * 8], Kl[128 * 8];   // [key][8 u32]
    __shared__ __align__(16) __nv_bfloat16 Vth[16 * 128], Vtl[16 * 128];  // [d][key]
    __shared__ float ms[128];

    const int tid = threadIdx.x;
    const int wid = tid >> 5, lane = tid & 31;
    const int g = lane >> 2, t = lane & 3;
    const int q0 = blockIdx.x * 128;
    const int h = blockIdx.y;
    const int b = blockIdx.z;

    const uint32_t* gqh = reinterpret_cast<const uint32_t*>(g_qh);
    const uint32_t* gql = reinterpret_cast<const uint32_t*>(g_ql);
    const uint32_t* gkh = reinterpret_cast<const uint32_t*>(g_kh);
    const uint32_t* gkl = reinterpret_cast<const uint32_t*>(g_kl);
    const uint32_t* gvh = reinterpret_cast<const uint32_t*>(g_vh);
    const uint32_t* gvl = reinterpret_cast<const uint32_t*>(g_vl);

    // load Q tile [128 x 16] hi/lo (u32 = 2 bf16; row = 128 u32 in global)
    #pragma unroll
    for (int i = tid; i < 1024; i += 256) {
        const int r = i >> 3, u = i & 7;
        const size_t gi = ((size_t)(b * Ss + q0 + r)) * 128 + h * 8 + u;
        Qh[r * 8 + u] = gqh[gi];
        Ql[r * 8 + u] = gql[gi];
    }
    __syncthreads();

    // persistent Q fragments for this warp's 16 rows
    const int wr = wid * 16;
    uint32_t qah[4], qal[4];
    qah[0] = Qh[(wr + g) * 8 + t];       qal[0] = Ql[(wr + g) * 8 + t];
    qah[1] = Qh[(wr + g + 8) * 8 + t];   qal[1] = Ql[(wr + g + 8) * 8 + t];
    qah[2] = Qh[(wr + g) * 8 + t + 4];   qal[2] = Ql[(wr + g) * 8 + t + 4];
    qah[3] = Qh[(wr + g + 8) * 8 + t + 4]; qal[3] = Ql[(wr + g + 8) * 8 + t + 4];

    float ctx[2][4];
    #pragma unroll
    for (int nn = 0; nn < 2; nn++)
        #pragma unroll
        for (int j = 0; j < 4; j++) ctx[nn][j] = 0.0f;
    float den0 = 0.0f, den1 = 0.0f;

    for (int c = 0; c < 4; c++) {
        if (c) __syncthreads();  // previous chunk's MMAs done with smem

        // load K chunk [128 x 16] hi/lo + V chunk transposed [16 d][128 key]
        #pragma unroll
        for (int i = tid; i < 1024; i += 256) {
            const int r = i >> 3, u = i & 7;
            const size_t gi = ((size_t)(b * Ss + c * 128 + r)) * 128 + h * 8 + u;
            Kh[r * 8 + u] = gkh[gi];
            Kl[r * 8 + u] = gkl[gi];
            const uint32_t vh = gvh[gi], vl = gvl[gi];
            Vth[(2 * u) * 128 + r]     = __ushort_as_bfloat16((unsigned short)(vh & 0xFFFF));
            Vth[(2 * u + 1) * 128 + r] = __ushort_as_bfloat16((unsigned short)(vh >> 16));
            Vtl[(2 * u) * 128 + r]     = __ushort_as_bfloat16((unsigned short)(vl & 0xFFFF));
            Vtl[(2 * u + 1) * 128 + r] = __ushort_as_bfloat16((unsigned short)(vl >> 16));
        }
        if (tid < 128) ms[tid] = mask[b * Ss + c * 128 + tid];
        __syncthreads();

        // QK^T: sc[nt] covers keys nt*8..nt*8+7 (fp32 accum; hh + hl + lh)
        float sc[16][4];
        #pragma unroll
        for (int nt = 0; nt < 16; nt++) {
            sc[nt][0] = sc[nt][1] = sc[nt][2] = sc[nt][3] = 0.0f;
            const int krow = (nt * 8 + g) * 8;
            const uint32_t b0h = Kh[krow + t], b1h = Kh[krow + t + 4];
            const uint32_t b0l = Kl[krow + t], b1l = Kl[krow + t + 4];
            mma_bf16(sc[nt], qah[0], qah[1], qah[2], qah[3], b0h, b1h);
            mma_bf16(sc[nt], qah[0], qah[1], qah[2], qah[3], b0l, b1l);
            mma_bf16(sc[nt], qal[0], qal[1], qal[2], qal[3], b0h, b1h);
        }

        // epilogue: p = exp(s/4)*mask, denominator accumulation (in place)
        #pragma unroll
        for (int nt = 0; nt < 16; nt++) {
            const float m0 = ms[nt * 8 + 2 * t];
            const float m1 = ms[nt * 8 + 2 * t + 1];
            const float p0 = __expf(sc[nt][0] * 0.25f) * m0;
            const float p1 = __expf(sc[nt][1] * 0.25f) * m1;
            const float p2 = __expf(sc[nt][2] * 0.25f) * m0;
            const float p3 = __expf(sc[nt][3] * 0.25f) * m1;
            den0 += p0 + p1;
            den1 += p2 + p3;
            sc[nt][0] = p0; sc[nt][1] = p1; sc[nt][2] = p2; sc[nt][3] = p3;
        }

        // P.V: D-frag layout == A-frag layout, so rebuild A from sc in regs
        const uint32_t* vth = reinterpret_cast<const uint32_t*>(Vth);
        const uint32_t* vtl = reinterpret_cast<const uint32_t*>(Vtl);
        #pragma unroll
        for (int kt = 0; kt < 8; kt++) {
            uint32_t pah[4], pal[4];
            pah[0] = bfsplit_pack(sc[2 * kt][0],     sc[2 * kt][1],     pal[0]);
            pah[1] = bfsplit_pack(sc[2 * kt][2],     sc[2 * kt][3],     pal[1]);
            pah[2] = bfsplit_pack(sc[2 * kt + 1][0], sc[2 * kt + 1][1], pal[2]);
            pah[3] = bfsplit_pack(sc[2 * kt + 1][2], sc[2 * kt + 1][3], pal[3]);
            #pragma unroll
            for (int nn = 0; nn < 2; nn++) {
                const int vrow = (nn * 8 + g) * 64;   // u32 stride per d-row = 64
                const uint32_t b0h = vth[vrow + kt * 8 + t], b1h = vth[vrow + kt * 8 + t + 4];
                const uint32_t b0l = vtl[vrow + kt * 8 + t], b1l = vtl[vrow + kt * 8 + t + 4];
                mma_bf16(ctx[nn], pah[0], pah[1], pah[2], pah[3], b0h, b1h);
                mma_bf16(ctx[nn], pah[0], pah[1], pah[2], pah[3], b0l, b1l);
                mma_bf16(ctx[nn], pal[0], pal[1], pal[2], pal[3], b0h, b1h);
            }
        }
    }

    // reduce denominator across the 4 lanes sharing a row (t = lane&3)
    den0 += __shfl_xor_sync(0xFFFFFFFFu, den0, 1);
    den0 += __shfl_xor_sync(0xFFFFFFFFu, den0, 2);
    den1 += __shfl_xor_sync(0xFFFFFFFFu, den1, 1);
    den1 += __shfl_xor_sync(0xFFFFFFFFu, den1, 2);
    const float i0 = 1.0f / (den0 + 1e-8f);
    const float i1 = 1.0f / (den1 + 1e-8f);

    // write ctx: rows (g, g+8), cols nn*8 + 2t, 2t+1
    const size_t row0 = (size_t)(b * Ss + q0 + wr + g);
    #pragma unroll
    for (int nn = 0; nn < 2; nn++) {
        float2 o0 = make_float2(ctx[nn][0] * i0, ctx[nn][1] * i0);
        float2 o1 = make_float2(ctx[nn][2] * i1, ctx[nn][3] * i1);
        *reinterpret_cast<float2*>(out + row0 * DM + h * DH + nn * 8 + 2 * t) = o0;
        *reinterpret_cast<float2*>(out + (row0 + 8) * DM + h * DH + nn * 8 + 2 * t) = o1;
    }
}

// ===========================================================================
extern "C" void kernel_launch(void* const* d_in, const int* in_sizes, int n_in,
                              void* d_out, int out_size)
{
    const float* Q    = (const float*)d_in[0];
    const float* K    = (const float*)d_in[1];
    const float* V    = (const float*)d_in[2];
    const float* mask = (const float*)d_in[3];
    const float* W_Q  = (const float*)d_in[4];
    const float* b_Q  = (const float*)d_in[5];
    const float* W_K  = (const float*)d_in[6];
    const float* b_K  = (const float*)d_in[7];
    const float* W_V  = (const float*)d_in[8];
    const float* b_V  = (const float*)d_in[9];
    float* out = (float*)d_out;

    dim3 gridP(DM / BN, Mrows / BM, 3);
    proj_gemm<<<gridP, 256>>>(Q, K, V, W_Q, W_K, W_V, b_Q, b_K, b_V);

    dim3 gridA(4, NH, Bb);
    attn_mma<<<gridA, 256>>>(mask, out);
}

// round 4
// speedup vs baseline: 1.7725x; 1.4240x over previous
#include <cuda_runtime.h>
#include <cuda_bf16.h>
#include <stdint.h>
#include <math.h>

// Problem constants
constexpr int Bb = 32;
constexpr int Ss = 512;
constexpr int DM = 256;     // d_model = H*d_k
constexpr int NH = 16;
constexpr int DH = 16;
constexpr int Mrows = Bb * Ss;  // 16384

// Scratch: split-bf16 projected q/k/v (hi + lo), layout [b*S+s][h*16+d]
__device__ __nv_bfloat16 g_qh[Mrows * DM], g_ql[Mrows * DM];
__device__ __nv_bfloat16 g_kh[Mrows * DM], g_kl[Mrows * DM];
__device__ __nv_bfloat16 g_vh[Mrows * DM], g_vl[Mrows * DM];

__device__ __forceinline__ uint32_t smem_u32(const void* p) {
    uint32_t a;
    asm("{ .reg .u64 t; cvta.to.shared.u64 t, %1; cvt.u32.u64 %0, t; }" : "=r"(a) : "l"(p));
    return a;
}

// split fp32 pair -> packed bf16 hi (return) + lo (out); a in low half
__device__ __forceinline__ uint32_t bfsplit_pack(float a, float b, uint32_t& lopack) {
    uint32_t hi;
    asm("cvt.rn.bf16x2.f32 %0, %1, %2;" : "=r"(hi) : "f"(b), "f"(a));
    float ar = a - __uint_as_float(hi << 16);
    float br = b - __uint_as_float(hi & 0xFFFF0000u);
    asm("cvt.rn.bf16x2.f32 %0, %1, %2;" : "=r"(lopack) : "f"(br), "f"(ar));
    return hi;
}

// m16n8k16 row.col bf16 MMA, fp32 accumulate in place
__device__ __forceinline__ void mma_bf16(float c[4], const uint32_t a[4],
                                         uint32_t b0, uint32_t b1) {
    asm volatile(
        "mma.sync.aligned.m16n8k16.row.col.f32.bf16.bf16.f32 "
        "{%0,%1,%2,%3}, {%4,%5,%6,%7}, {%8,%9}, {%0,%1,%2,%3};\n"
        : "+f"(c[0]), "+f"(c[1]), "+f"(c[2]), "+f"(c[3])
        : "r"(a[0]), "r"(a[1]), "r"(a[2]), "r"(a[3]), "r"(b0), "r"(b1));
}

__device__ __forceinline__ void ldm_x4(uint32_t r[4], uint32_t addr) {
    asm volatile("ldmatrix.sync.aligned.m8n8.x4.shared.b16 {%0,%1,%2,%3}, [%4];"
                 : "=r"(r[0]), "=r"(r[1]), "=r"(r[2]), "=r"(r[3]) : "r"(addr));
}
__device__ __forceinline__ void ldm_x4_t(uint32_t r[4], uint32_t addr) {
    asm volatile("ldmatrix.sync.aligned.m8n8.x4.trans.shared.b16 {%0,%1,%2,%3}, [%4];"
                 : "=r"(r[0]), "=r"(r[1]), "=r"(r[2]), "=r"(r[3]) : "r"(addr));
}

// ===========================================================================
// Projection GEMM (fp32 compute); epilogue writes split-bf16 hi/lo.
// ===========================================================================
#define BM 128
#define BN 128
#define BKq 8
#define TM 8
#define TN 8

__global__ __launch_bounds__(256) void proj_gemm(
    const float* __restrict__ Qin, const float* __restrict__ Kin, const float* __restrict__ Vin,
    const float* __restrict__ WQ,  const float* __restrict__ WK,  const float* __restrict__ WV,
    const float* __restrict__ bQ,  const float* __restrict__ bK,  const float* __restrict__ bV)
{
    const float* A; const float* W; const float* bias;
    __nv_bfloat16 *Ch, *Cl;
    if (blockIdx.z == 0)      { A = Qin; W = WQ; bias = bQ; Ch = g_qh; Cl = g_ql; }
    else if (blockIdx.z == 1) { A = Kin; W = WK; bias = bK; Ch = g_kh; Cl = g_kl; }
    else                      { A = Vin; W = WV; bias = bV; Ch = g_vh; Cl = g_vl; }

    __shared__ float As[BKq][BM];
    __shared__ float Bs[BKq][BN];

    const int K = DM, N = DM;
    const int tid = threadIdx.x;
    const int tx = tid & 15;
    const int ty = tid >> 4;
    const int row0 = blockIdx.y * BM;
    const int col0 = blockIdx.x * BN;
    const int lRow = tid >> 1;
    const int lCol = (tid & 1) * 4;

    float acc[TM][TN];
    #pragma unroll
    for (int i = 0; i < TM; i++)
        #pragma unroll
        for (int j = 0; j < TN; j++) acc[i][j] = 0.0f;

    for (int kt = 0; kt < K; kt += BKq) {
        float4 a = *reinterpret_cast<const float4*>(A + (size_t)(row0 + lRow) * K + kt + lCol);
        As[lCol + 0][lRow] = a.x; As[lCol + 1][lRow] = a.y;
        As[lCol + 2][lRow] = a.z; As[lCol + 3][lRow] = a.w;
        float4 w = *reinterpret_cast<const float4*>(W + (size_t)(col0 + lRow) * K + kt + lCol);
        Bs[lCol + 0][lRow] = w.x; Bs[lCol + 1][lRow] = w.y;
        Bs[lCol + 2][lRow] = w.z; Bs[lCol + 3][lRow] = w.w;
        __syncthreads();

        #pragma unroll
        for (int k = 0; k < BKq; k++) {
            float4 m0 = *reinterpret_cast<const float4*>(&As[k][ty * TM]);
            float4 m1 = *reinterpret_cast<const float4*>(&As[k][ty * TM + 4]);
            float4 n0 = *reinterpret_cast<const float4*>(&Bs[k][tx * TN]);
            float4 n1 = *reinterpret_cast<const float4*>(&Bs[k][tx * TN + 4]);
            float rm[8] = {m0.x, m0.y, m0.z, m0.w, m1.x, m1.y, m1.z, m1.w};
            float rn[8] = {n0.x, n0.y, n0.z, n0.w, n1.x, n1.y, n1.z, n1.w};
            #pragma unroll
            for (int i = 0; i < TM; i++)
                #pragma unroll
                for (int j = 0; j < TN; j++)
                    acc[i][j] += rm[i] * rn[j];
        }
        __syncthreads();
    }

    float bj[TN];
    #pragma unroll
    for (int j = 0; j < TN; j++) bj[j] = bias[col0 + tx * TN + j];

    #pragma unroll
    for (int i = 0; i < TM; i++) {
        const size_t off = (size_t)(row0 + ty * TM + i) * N + col0 + tx * TN;
        uint4 hi, lo;
        hi.x = bfsplit_pack(acc[i][0] + bj[0], acc[i][1] + bj[1], lo.x);
        hi.y = bfsplit_pack(acc[i][2] + bj[2], acc[i][3] + bj[3], lo.y);
        hi.z = bfsplit_pack(acc[i][4] + bj[4], acc[i][5] + bj[5], lo.z);
        hi.w = bfsplit_pack(acc[i][6] + bj[6], acc[i][7] + bj[7], lo.w);
        *reinterpret_cast<uint4*>(Ch + off) = hi;
        *reinterpret_cast<uint4*>(Cl + off) = lo;
    }
}

// ===========================================================================
// Attention via mma.sync + ldmatrix, fused QK->exp->PV per 16-key step.
// CTA = (q-tile 128, head, batch); 8 warps x 16 q-rows; 4 key chunks of 128.
// Smem rows padded to 48B (12 u32) -> conflict-free ldmatrix.
// ===========================================================================
constexpr int ROWU = 12;   // u32 stride per 16-bf16 row (48 B)

__global__ __launch_bounds__(256, 3) void attn_mma(const float* __restrict__ mask,
                                                   float* __restrict__ out)
{
    __shared__ __align__(16) uint32_t Qh[128 * ROWU], Ql[128 * ROWU];
    __shared__ __align__(16) uint32_t Kh[128 * ROWU], Kl[128 * ROWU];
    __shared__ __align__(16) uint32_t Vh[128 * ROWU], Vl[128 * ROWU];
    __shared__ float ms[128];

    const int tid = threadIdx.x;
    const int wid = tid >> 5, lane = tid & 31;
    const int g = lane >> 2, t = lane & 3;
    const int q0 = blockIdx.x * 128;
    const int h = blockIdx.y;
    const int b = blockIdx.z;

    const uint32_t* gqh = reinterpret_cast<const uint32_t*>(g_qh);
    const uint32_t* gql = reinterpret_cast<const uint32_t*>(g_ql);
    const uint32_t* gkh = reinterpret_cast<const uint32_t*>(g_kh);
    const uint32_t* gkl = reinterpret_cast<const uint32_t*>(g_kl);
    const uint32_t* gvh = reinterpret_cast<const uint32_t*>(g_vh);
    const uint32_t* gvl = reinterpret_cast<const uint32_t*>(g_vl);

    // ldmatrix lane->address offsets (bytes)
    // K (non-trans B-frags): tiles (b0 nt0, b1 nt0, b0 nt1, b1 nt1)
    const uint32_t okk = ((lane & 7) + ((lane >> 4) << 3)) * 48 + (((lane >> 3) & 1) << 4);
    // V (trans B-frags): tiles (b0 nn0, b1 nn0, b0 nn1, b1 nn1)
    const uint32_t okv = ((lane & 7) + (((lane >> 3) & 1) << 3)) * 48 + ((lane >> 4) << 4);
    // Q (A-frags): tiles (a0, a1, a2, a3)
    const uint32_t okq = (wid * 16 + (lane & 7) + (((lane >> 3) & 1) << 3)) * 48 + ((lane >> 4) << 4);

    const uint32_t sKh = smem_u32(Kh) + okk, sKl = smem_u32(Kl) + okk;
    const uint32_t sVh = smem_u32(Vh) + okv, sVl = smem_u32(Vl) + okv;

    // load Q tile [128 x 16] hi/lo (uint2 per thread-iter)
    #pragma unroll
    for (int i = tid; i < 512; i += 256) {
        const int r = i >> 2, u = (i & 3) * 2;
        const size_t gi = ((size_t)(b * Ss + q0 + r)) * 128 + h * 8 + u;
        *reinterpret_cast<uint2*>(&Qh[r * ROWU + u]) = *reinterpret_cast<const uint2*>(gqh + gi);
        *reinterpret_cast<uint2*>(&Ql[r * ROWU + u]) = *reinterpret_cast<const uint2*>(gql + gi);
    }
    __syncthreads();

    uint32_t qah[4], qal[4];
    ldm_x4(qah, smem_u32(Qh) + okq);
    ldm_x4(qal, smem_u32(Ql) + okq);

    float ctx0[4] = {0.f, 0.f, 0.f, 0.f};
    float ctx1[4] = {0.f, 0.f, 0.f, 0.f};
    float den0 = 0.0f, den1 = 0.0f;

    for (int c = 0; c < 4; c++) {
        __syncthreads();  // previous chunk's reads done (Q load sync covers c=0)

        #pragma unroll
        for (int i = tid; i < 512; i += 256) {
            const int r = i >> 2, u = (i & 3) * 2;
            const size_t gi = ((size_t)(b * Ss + c * 128 + r)) * 128 + h * 8 + u;
            *reinterpret_cast<uint2*>(&Kh[r * ROWU + u]) = *reinterpret_cast<const uint2*>(gkh + gi);
            *reinterpret_cast<uint2*>(&Kl[r * ROWU + u]) = *reinterpret_cast<const uint2*>(gkl + gi);
            *reinterpret_cast<uint2*>(&Vh[r * ROWU + u]) = *reinterpret_cast<const uint2*>(gvh + gi);
            *reinterpret_cast<uint2*>(&Vl[r * ROWU + u]) = *reinterpret_cast<const uint2*>(gvl + gi);
        }
        if (tid < 128) ms[tid] = mask[b * Ss + c * 128 + tid];
        __syncthreads();

        #pragma unroll
        for (int kt = 0; kt < 8; kt++) {
            // ---- QK^T for 16 keys (nt0 = 2kt, nt1 = 2kt+1) ----
            uint32_t bh[4], bl[4];
            ldm_x4(bh, sKh + kt * 768);
            ldm_x4(bl, sKl + kt * 768);
            float sc0[4] = {0.f, 0.f, 0.f, 0.f};
            float sc1[4] = {0.f, 0.f, 0.f, 0.f};
            mma_bf16(sc0, qah, bh[0], bh[1]);
            mma_bf16(sc0, qah, bl[0], bl[1]);
            mma_bf16(sc0, qal, bh[0], bh[1]);
            mma_bf16(sc1, qah, bh[2], bh[3]);
            mma_bf16(sc1, qah, bl[2], bl[3]);
            mma_bf16(sc1, qal, bh[2], bh[3]);

            // ---- epilogue: p = exp(s/4)*mask, denom ----
            const float m0 = ms[kt * 16 + 2 * t];
            const float m1 = ms[kt * 16 + 2 * t + 1];
            const float m2 = ms[kt * 16 + 8 + 2 * t];
            const float m3 = ms[kt * 16 + 8 + 2 * t + 1];
            const float p00 = __expf(sc0[0] * 0.25f) * m0;
            const float p01 = __expf(sc0[1] * 0.25f) * m1;
            const float p02 = __expf(sc0[2] * 0.25f) * m0;
            const float p03 = __expf(sc0[3] * 0.25f) * m1;
            const float p10 = __expf(sc1[0] * 0.25f) * m2;
            const float p11 = __expf(sc1[1] * 0.25f) * m3;
            const float p12 = __expf(sc1[2] * 0.25f) * m2;
            const float p13 = __expf(sc1[3] * 0.25f) * m3;
            den0 += p00 + p01 + p10 + p11;
            den1 += p02 + p03 + p12 + p13;

            uint32_t pah[4], pal[4];
            pah[0] = bfsplit_pack(p00, p01, pal[0]);
            pah[1] = bfsplit_pack(p02, p03, pal[1]);
            pah[2] = bfsplit_pack(p10, p11, pal[2]);
            pah[3] = bfsplit_pack(p12, p13, pal[3]);

            // ---- P.V for these 16 keys ----
            uint32_t vh[4], vl[4];
            ldm_x4_t(vh, sVh + kt * 768);
            ldm_x4_t(vl, sVl + kt * 768);
            mma_bf16(ctx0, pah, vh[0], vh[1]);
            mma_bf16(ctx0, pah, vl[0], vl[1]);
            mma_bf16(ctx0, pal, vh[0], vh[1]);
            mma_bf16(ctx1, pah, vh[2], vh[3]);
            mma_bf16(ctx1, pah, vl[2], vl[3]);
            mma_bf16(ctx1, pal, vh[2], vh[3]);
        }
    }

    // reduce denominator across the 4 lanes sharing each row
    den0 += __shfl_xor_sync(0xFFFFFFFFu, den0, 1);
    den0 += __shfl_xor_sync(0xFFFFFFFFu, den0, 2);
    den1 += __shfl_xor_sync(0xFFFFFFFFu, den1, 1);
    den1 += __shfl_xor_sync(0xFFFFFFFFu, den1, 2);
    const float i0 = 1.0f / (den0 + 1e-8f);
    const float i1 = 1.0f / (den1 + 1e-8f);

    // write ctx: rows (g, g+8), cols nn*8 + 2t, 2t+1
    const size_t row0 = (size_t)(b * Ss + q0 + wid * 16 + g);
    {
        float2 o00 = make_float2(ctx0[0] * i0, ctx0[1] * i0);
        float2 o01 = make_float2(ctx0[2] * i1, ctx0[3] * i1);
        float2 o10 = make_float2(ctx1[0] * i0, ctx1[1] * i0);
        float2 o11 = make_float2(ctx1[2] * i1, ctx1[3] * i1);
        *reinterpret_cast<float2*>(out + row0 * DM + h * DH + 2 * t) = o00;
        *reinterpret_cast<float2*>(out + (row0 + 8) * DM + h * DH + 2 * t) = o01;
        *reinterpret_cast<float2*>(out + row0 * DM + h * DH + 8 + 2 * t) = o10;
        *reinterpret_cast<float2*>(out + (row0 + 8) * DM + h * DH + 8 + 2 * t) = o11;
    }
}

// ===========================================================================
extern "C" void kernel_launch(void* const* d_in, const int* in_sizes, int n_in,
                              void* d_out, int out_size)
{
    const float* Q    = (const float*)d_in[0];
    const float* K    = (const float*)d_in[1];
    const float* V    = (const float*)d_in[2];
    const float* mask = (const float*)d_in[3];
    const float* W_Q  = (const float*)d_in[4];
    const float* b_Q  = (const float*)d_in[5];
    const float* W_K  = (const float*)d_in[6];
    const float* b_K  = (const float*)d_in[7];
    const float* W_V  = (const float*)d_in[8];
    const float* b_V  = (const float*)d_in[9];
    float* out = (float*)d_out;

    dim3 gridP(DM / BN, Mrows / BM, 3);
    proj_gemm<<<gridP, 256>>>(Q, K, V, W_Q, W_K, W_V, b_Q, b_K, b_V);

    dim3 gridA(4, NH, Bb);
    attn_mma<<<gridA, 256>>>(mask, out);
}

// round 5
// speedup vs baseline: 2.6969x; 1.5216x over previous
#include <cuda_runtime.h>
#include <cuda_bf16.h>
#include <stdint.h>
#include <math.h>

// Problem constants
constexpr int Bb = 32;
constexpr int Ss = 512;
constexpr int DM = 256;     // d_model = H*d_k
constexpr int NH = 16;
constexpr int DH = 16;
constexpr int Mrows = Bb * Ss;  // 16384

// Scratch: split-bf16 projected q/k/v (hi + lo), layout [b*S+s][h*16+d]
__device__ __nv_bfloat16 g_qh[Mrows * DM], g_ql[Mrows * DM];
__device__ __nv_bfloat16 g_kh[Mrows * DM], g_kl[Mrows * DM];
__device__ __nv_bfloat16 g_vh[Mrows * DM], g_vl[Mrows * DM];

__device__ __forceinline__ uint32_t smem_u32(const void* p) {
    uint32_t a;
    asm("{ .reg .u64 t; cvta.to.shared.u64 t, %1; cvt.u32.u64 %0, t; }" : "=r"(a) : "l"(p));
    return a;
}

// split fp32 pair -> packed bf16 hi (return) + lo (out); a in low half
__device__ __forceinline__ uint32_t bfsplit_pack(float a, float b, uint32_t& lopack) {
    uint32_t hi;
    asm("cvt.rn.bf16x2.f32 %0, %1, %2;" : "=r"(hi) : "f"(b), "f"(a));
    float ar = a - __uint_as_float(hi << 16);
    float br = b - __uint_as_float(hi & 0xFFFF0000u);
    asm("cvt.rn.bf16x2.f32 %0, %1, %2;" : "=r"(lopack) : "f"(br), "f"(ar));
    return hi;
}

// m16n8k16 row.col bf16 MMA, fp32 accumulate in place
__device__ __forceinline__ void mma_bf16(float c[4], const uint32_t a[4],
                                         uint32_t b0, uint32_t b1) {
    asm volatile(
        "mma.sync.aligned.m16n8k16.row.col.f32.bf16.bf16.f32 "
        "{%0,%1,%2,%3}, {%4,%5,%6,%7}, {%8,%9}, {%0,%1,%2,%3};\n"
        : "+f"(c[0]), "+f"(c[1]), "+f"(c[2]), "+f"(c[3])
        : "r"(a[0]), "r"(a[1]), "r"(a[2]), "r"(a[3]), "r"(b0), "r"(b1));
}

__device__ __forceinline__ void ldm_x4(uint32_t r[4], uint32_t addr) {
    asm volatile("ldmatrix.sync.aligned.m8n8.x4.shared.b16 {%0,%1,%2,%3}, [%4];"
                 : "=r"(r[0]), "=r"(r[1]), "=r"(r[2]), "=r"(r[3]) : "r"(addr));
}
__device__ __forceinline__ void ldm_x4_t(uint32_t r[4], uint32_t addr) {
    asm volatile("ldmatrix.sync.aligned.m8n8.x4.trans.shared.b16 {%0,%1,%2,%3}, [%4];"
                 : "=r"(r[0]), "=r"(r[1]), "=r"(r[2]), "=r"(r[3]) : "r"(addr));
}

// ===========================================================================
// Projection GEMM via mma.sync, split-bf16 (hh + lh + hl).
// CTA = 128M x 128N, K-loop 8 x 32. Warps: 4(M) x 2(N); warp = 32M x 64N.
// fp32 A and W converted to split-bf16 in the tile loader.
// Smem rows padded to 80B (20 u32) -> conflict-free ldmatrix.
// ===========================================================================
constexpr int RW = 20;  // u32 per 32-bf16 row (80 B)

__global__ __launch_bounds__(256, 2) void proj_mma(
    const float* __restrict__ Qin, const float* __restrict__ Kin, const float* __restrict__ Vin,
    const float* __restrict__ WQ,  const float* __restrict__ WK,  const float* __restrict__ WV,
    const float* __restrict__ bQ,  const float* __restrict__ bK,  const float* __restrict__ bV)
{
    __shared__ __align__(16) uint32_t Ah[128 * RW], Al[128 * RW];
    __shared__ __align__(16) uint32_t Wh[128 * RW], Wl[128 * RW];

    const float* A; const float* W; const float* bias;
    __nv_bfloat16 *Ch, *Cl;
    if (blockIdx.z == 0)      { A = Qin; W = WQ; bias = bQ; Ch = g_qh; Cl = g_ql; }
    else if (blockIdx.z == 1) { A = Kin; W = WK; bias = bK; Ch = g_kh; Cl = g_kl; }
    else                      { A = Vin; W = WV; bias = bV; Ch = g_vh; Cl = g_vl; }

    const int tid = threadIdx.x;
    const int wid = tid >> 5, lane = tid & 31;
    const int warpM = wid >> 1, warpN = wid & 1;
    const int row0 = blockIdx.y * 128;
    const int col0 = blockIdx.x * 128;

    // ldmatrix lane offsets (bytes)
    const uint32_t okA = (uint32_t)(warpM * 32 + (lane & 15)) * 80 + ((lane >> 4) << 4);
    const uint32_t okB = (uint32_t)(warpN * 64 + (lane & 7) + ((lane >> 4) << 3)) * 80
                       + (((lane >> 3) & 1) << 4);
    const uint32_t sAh = smem_u32(Ah) + okA, sAl = smem_u32(Al) + okA;
    const uint32_t sWh = smem_u32(Wh) + okB, sWl = smem_u32(Wl) + okB;

    // loader assignment: thread -> (row = tid>>1, 16-col segment = (tid&1)*16)
    const int lr = tid >> 1, sg = (tid & 1) * 16;

    float acc[2][8][4];
    #pragma unroll
    for (int m = 0; m < 2; m++)
        #pragma unroll
        for (int nt = 0; nt < 8; nt++)
            #pragma unroll
            for (int j = 0; j < 4; j++) acc[m][nt][j] = 0.0f;

    for (int it = 0; it < 8; it++) {
        if (it) __syncthreads();

        // --- load + split-convert A chunk [128 x 32] and W chunk [128 x 32] ---
        {
            const float* srcA = A + (size_t)(row0 + lr) * DM + it * 32 + sg;
            const float* srcW = W + (size_t)(col0 + lr) * DM + it * 32 + sg;
            uint4 h0, h1, l0, l1;
            float4 f0 = *reinterpret_cast<const float4*>(srcA);
            float4 f1 = *reinterpret_cast<const float4*>(srcA + 4);
            float4 f2 = *reinterpret_cast<const float4*>(srcA + 8);
            float4 f3 = *reinterpret_cast<const float4*>(srcA + 12);
            h0.x = bfsplit_pack(f0.x, f0.y, l0.x); h0.y = bfsplit_pack(f0.z, f0.w, l0.y);
            h0.z = bfsplit_pack(f1.x, f1.y, l0.z); h0.w = bfsplit_pack(f1.z, f1.w, l0.w);
            h1.x = bfsplit_pack(f2.x, f2.y, l1.x); h1.y = bfsplit_pack(f2.z, f2.w, l1.y);
            h1.z = bfsplit_pack(f3.x, f3.y, l1.z); h1.w = bfsplit_pack(f3.z, f3.w, l1.w);
            const int so = lr * RW + sg / 2;
            *reinterpret_cast<uint4*>(&Ah[so]) = h0; *reinterpret_cast<uint4*>(&Ah[so + 4]) = h1;
            *reinterpret_cast<uint4*>(&Al[so]) = l0; *reinterpret_cast<uint4*>(&Al[so + 4]) = l1;

            f0 = *reinterpret_cast<const float4*>(srcW);
            f1 = *reinterpret_cast<const float4*>(srcW + 4);
            f2 = *reinterpret_cast<const float4*>(srcW + 8);
            f3 = *reinterpret_cast<const float4*>(srcW + 12);
            h0.x = bfsplit_pack(f0.x, f0.y, l0.x); h0.y = bfsplit_pack(f0.z, f0.w, l0.y);
            h0.z = bfsplit_pack(f1.x, f1.y, l0.z); h0.w = bfsplit_pack(f1.z, f1.w, l0.w);
            h1.x = bfsplit_pack(f2.x, f2.y, l1.x); h1.y = bfsplit_pack(f2.z, f2.w, l1.y);
            h1.z = bfsplit_pack(f3.x, f3.y, l1.z); h1.w = bfsplit_pack(f3.z, f3.w, l1.w);
            *reinterpret_cast<uint4*>(&Wh[so]) = h0; *reinterpret_cast<uint4*>(&Wh[so + 4]) = h1;
            *reinterpret_cast<uint4*>(&Wl[so]) = l0; *reinterpret_cast<uint4*>(&Wl[so + 4]) = l1;
        }
        __syncthreads();

        #pragma unroll
        for (int ks = 0; ks < 2; ks++) {
            uint32_t aah[2][4], aal[2][4];
            ldm_x4(aah[0], sAh + ks * 32);
            ldm_x4(aal[0], sAl + ks * 32);
            ldm_x4(aah[1], sAh + 16 * 80 + ks * 32);
            ldm_x4(aal[1], sAl + 16 * 80 + ks * 32);

            #pragma unroll
            for (int np = 0; np < 4; np++) {
                uint32_t bh[4], bl[4];
                ldm_x4(bh, sWh + np * 16 * 80 + ks * 32);
                ldm_x4(bl, sWl + np * 16 * 80 + ks * 32);
                #pragma unroll
                for (int m = 0; m < 2; m++) {
                    mma_bf16(acc[m][2 * np],     aah[m], bh[0], bh[1]);
                    mma_bf16(acc[m][2 * np],     aal[m], bh[0], bh[1]);
                    mma_bf16(acc[m][2 * np],     aah[m], bl[0], bl[1]);
                    mma_bf16(acc[m][2 * np + 1], aah[m], bh[2], bh[3]);
                    mma_bf16(acc[m][2 * np + 1], aal[m], bh[2], bh[3]);
                    mma_bf16(acc[m][2 * np + 1], aah[m], bl[2], bl[3]);
                }
            }
        }
    }

    // epilogue: bias add + split-bf16 store
    const int tq = lane & 3, g8 = lane >> 2;
    #pragma unroll
    for (int m = 0; m < 2; m++) {
        const size_t r0 = (size_t)(row0 + warpM * 32 + m * 16 + g8);
        #pragma unroll
        for (int nt = 0; nt < 8; nt++) {
            const int c = col0 + warpN * 64 + nt * 8 + 2 * tq;
            const float b0 = bias[c], b1 = bias[c + 1];
            uint32_t lo0, lo1;
            uint32_t hi0 = bfsplit_pack(acc[m][nt][0] + b0, acc[m][nt][1] + b1, lo0);
            uint32_t hi1 = bfsplit_pack(acc[m][nt][2] + b0, acc[m][nt][3] + b1, lo1);
            *reinterpret_cast<uint32_t*>(Ch + r0 * DM + c) = hi0;
            *reinterpret_cast<uint32_t*>(Cl + r0 * DM + c) = lo0;
            *reinterpret_cast<uint32_t*>(Ch + (r0 + 8) * DM + c) = hi1;
            *reinterpret_cast<uint32_t*>(Cl + (r0 + 8) * DM + c) = lo1;
        }
    }
}

// ===========================================================================
// Attention via mma.sync + ldmatrix, fused QK->exp->PV per 16-key step.
// (unchanged from round 4: 106.7us, tensor 39.5%)
// ===========================================================================
constexpr int ROWU = 12;   // u32 stride per 16-bf16 row (48 B)

__global__ __launch_bounds__(256, 3) void attn_mma(const float* __restrict__ mask,
                                                   float* __restrict__ out)
{
    __shared__ __align__(16) uint32_t Qh[128 * ROWU], Ql[128 * ROWU];
    __shared__ __align__(16) uint32_t Kh[128 * ROWU], Kl[128 * ROWU];
    __shared__ __align__(16) uint32_t Vh[128 * ROWU], Vl[128 * ROWU];
    __shared__ float ms[128];

    const int tid = threadIdx.x;
    const int wid = tid >> 5, lane = tid & 31;
    const int t = lane & 3;
    const int q0 = blockIdx.x * 128;
    const int h = blockIdx.y;
    const int b = blockIdx.z;

    const uint32_t* gqh = reinterpret_cast<const uint32_t*>(g_qh);
    const uint32_t* gql = reinterpret_cast<const uint32_t*>(g_ql);
    const uint32_t* gkh = reinterpret_cast<const uint32_t*>(g_kh);
    const uint32_t* gkl = reinterpret_cast<const uint32_t*>(g_kl);
    const uint32_t* gvh = reinterpret_cast<const uint32_t*>(g_vh);
    const uint32_t* gvl = reinterpret_cast<const uint32_t*>(g_vl);

    const uint32_t okk = ((lane & 7) + ((lane >> 4) << 3)) * 48 + (((lane >> 3) & 1) << 4);
    const uint32_t okv = ((lane & 7) + (((lane >> 3) & 1) << 3)) * 48 + ((lane >> 4) << 4);
    const uint32_t okq = (wid * 16 + (lane & 7) + (((lane >> 3) & 1) << 3)) * 48 + ((lane >> 4) << 4);

    const uint32_t sKh = smem_u32(Kh) + okk, sKl = smem_u32(Kl) + okk;
    const uint32_t sVh = smem_u32(Vh) + okv, sVl = smem_u32(Vl) + okv;

    #pragma unroll
    for (int i = tid; i < 512; i += 256) {
        const int r = i >> 2, u = (i & 3) * 2;
        const size_t gi = ((size_t)(b * Ss + q0 + r)) * 128 + h * 8 + u;
        *reinterpret_cast<uint2*>(&Qh[r * ROWU + u]) = *reinterpret_cast<const uint2*>(gqh + gi);
        *reinterpret_cast<uint2*>(&Ql[r * ROWU + u]) = *reinterpret_cast<const uint2*>(gql + gi);
    }
    __syncthreads();

    uint32_t qah[4], qal[4];
    ldm_x4(qah, smem_u32(Qh) + okq);
    ldm_x4(qal, smem_u32(Ql) + okq);

    float ctx0[4] = {0.f, 0.f, 0.f, 0.f};
    float ctx1[4] = {0.f, 0.f, 0.f, 0.f};
    float den0 = 0.0f, den1 = 0.0f;

    for (int c = 0; c < 4; c++) {
        __syncthreads();

        #pragma unroll
        for (int i = tid; i < 512; i += 256) {
            const int r = i >> 2, u = (i & 3) * 2;
            const size_t gi = ((size_t)(b * Ss + c * 128 + r)) * 128 + h * 8 + u;
            *reinterpret_cast<uint2*>(&Kh[r * ROWU + u]) = *reinterpret_cast<const uint2*>(gkh + gi);
            *reinterpret_cast<uint2*>(&Kl[r * ROWU + u]) = *reinterpret_cast<const uint2*>(gkl + gi);
            *reinterpret_cast<uint2*>(&Vh[r * ROWU + u]) = *reinterpret_cast<const uint2*>(gvh + gi);
            *reinterpret_cast<uint2*>(&Vl[r * ROWU + u]) = *reinterpret_cast<const uint2*>(gvl + gi);
        }
        if (tid < 128) ms[tid] = mask[b * Ss + c * 128 + tid];
        __syncthreads();

        #pragma unroll
        for (int kt = 0; kt < 8; kt++) {
            uint32_t bh[4], bl[4];
            ldm_x4(bh, sKh + kt * 768);
            ldm_x4(bl, sKl + kt * 768);
            float sc0[4] = {0.f, 0.f, 0.f, 0.f};
            float sc1[4] = {0.f, 0.f, 0.f, 0.f};
            mma_bf16(sc0, qah, bh[0], bh[1]);
            mma_bf16(sc0, qah, bl[0], bl[1]);
            mma_bf16(sc0, qal, bh[0], bh[1]);
            mma_bf16(sc1, qah, bh[2], bh[3]);
            mma_bf16(sc1, qah, bl[2], bl[3]);
            mma_bf16(sc1, qal, bh[2], bh[3]);

            const float m0 = ms[kt * 16 + 2 * t];
            const float m1 = ms[kt * 16 + 2 * t + 1];
            const float m2 = ms[kt * 16 + 8 + 2 * t];
            const float m3 = ms[kt * 16 + 8 + 2 * t + 1];
            const float p00 = __expf(sc0[0] * 0.25f) * m0;
            const float p01 = __expf(sc0[1] * 0.25f) * m1;
            const float p02 = __expf(sc0[2] * 0.25f) * m0;
            const float p03 = __expf(sc0[3] * 0.25f) * m1;
            const float p10 = __expf(sc1[0] * 0.25f) * m2;
            const float p11 = __expf(sc1[1] * 0.25f) * m3;
            const float p12 = __expf(sc1[2] * 0.25f) * m2;
            const float p13 = __expf(sc1[3] * 0.25f) * m3;
            den0 += p00 + p01 + p10 + p11;
            den1 += p02 + p03 + p12 + p13;

            uint32_t pah[4], pal[4];
            pah[0] = bfsplit_pack(p00, p01, pal[0]);
            pah[1] = bfsplit_pack(p02, p03, pal[1]);
            pah[2] = bfsplit_pack(p10, p11, pal[2]);
            pah[3] = bfsplit_pack(p12, p13, pal[3]);

            uint32_t vh[4], vl[4];
            ldm_x4_t(vh, sVh + kt * 768);
            ldm_x4_t(vl, sVl + kt * 768);
            mma_bf16(ctx0, pah, vh[0], vh[1]);
            mma_bf16(ctx0, pah, vl[0], vl[1]);
            mma_bf16(ctx0, pal, vh[0], vh[1]);
            mma_bf16(ctx1, pah, vh[2], vh[3]);
            mma_bf16(ctx1, pah, vl[2], vl[3]);
            mma_bf16(ctx1, pal, vh[2], vh[3]);
        }
    }

    den0 += __shfl_xor_sync(0xFFFFFFFFu, den0, 1);
    den0 += __shfl_xor_sync(0xFFFFFFFFu, den0, 2);
    den1 += __shfl_xor_sync(0xFFFFFFFFu, den1, 1);
    den1 += __shfl_xor_sync(0xFFFFFFFFu, den1, 2);
    const float i0 = 1.0f / (den0 + 1e-8f);
    const float i1 = 1.0f / (den1 + 1e-8f);

    const int g = lane >> 2;
    const size_t row0 = (size_t)(b * Ss + q0 + wid * 16 + g);
    {
        float2 o00 = make_float2(ctx0[0] * i0, ctx0[1] * i0);
        float2 o01 = make_float2(ctx0[2] * i1, ctx0[3] * i1);
        float2 o10 = make_float2(ctx1[0] * i0, ctx1[1] * i0);
        float2 o11 = make_float2(ctx1[2] * i1, ctx1[3] * i1);
        *reinterpret_cast<float2*>(out + row0 * DM + h * DH + 2 * t) = o00;
        *reinterpret_cast<float2*>(out + (row0 + 8) * DM + h * DH + 2 * t) = o01;
        *reinterpret_cast<float2*>(out + row0 * DM + h * DH + 8 + 2 * t) = o10;
        *reinterpret_cast<float2*>(out + (row0 + 8) * DM + h * DH + 8 + 2 * t) = o11;
    }
}

// ===========================================================================
extern "C" void kernel_launch(void* const* d_in, const int* in_sizes, int n_in,
                              void* d_out, int out_size)
{
    const float* Q    = (const float*)d_in[0];
    const float* K    = (const float*)d_in[1];
    const float* V    = (const float*)d_in[2];
    const float* mask = (const float*)d_in[3];
    const float* W_Q  = (const float*)d_in[4];
    const float* b_Q  = (const float*)d_in[5];
    const float* W_K  = (const float*)d_in[6];
    const float* b_K  = (const float*)d_in[7];
    const float* W_V  = (const float*)d_in[8];
    const float* b_V  = (const float*)d_in[9];
    float* out = (float*)d_out;

    dim3 gridP(2, Mrows / 128, 3);   // (N-tile, M-tile, which projection)
    proj_mma<<<gridP, 256>>>(Q, K, V, W_Q, W_K, W_V, b_Q, b_K, b_V);

    dim3 gridA(4, NH, Bb);
    attn_mma<<<gridA, 256>>>(mask, out);
}

// round 6
// speedup vs baseline: 2.9174x; 1.0817x over previous
#include <cuda_runtime.h>
#include <cuda_bf16.h>
#include <stdint.h>
#include <math.h>

// Problem constants
constexpr int Bb = 32;
constexpr int Ss = 512;
constexpr int DM = 256;     // d_model = H*d_k
constexpr int NH = 16;
constexpr int DH = 16;
constexpr int Mrows = Bb * Ss;  // 16384

// Scratch: split-bf16 projected q/k/v (hi + lo), layout [b*S+s][h*16+d]
// NOTE: q is pre-scaled by 0.25*log2(e) so attention uses raw ex2.
__device__ __nv_bfloat16 g_qh[Mrows * DM], g_ql[Mrows * DM];
__device__ __nv_bfloat16 g_kh[Mrows * DM], g_kl[Mrows * DM];
__device__ __nv_bfloat16 g_vh[Mrows * DM], g_vl[Mrows * DM];

__device__ __forceinline__ uint32_t smem_u32(const void* p) {
    uint32_t a;
    asm("{ .reg .u64 t; cvta.to.shared.u64 t, %1; cvt.u32.u64 %0, t; }" : "=r"(a) : "l"(p));
    return a;
}

// split fp32 pair -> packed bf16 hi (return) + lo (out); a in low half
__device__ __forceinline__ uint32_t bfsplit_pack(float a, float b, uint32_t& lopack) {
    uint32_t hi;
    asm("cvt.rn.bf16x2.f32 %0, %1, %2;" : "=r"(hi) : "f"(b), "f"(a));
    float ar = a - __uint_as_float(hi << 16);
    float br = b - __uint_as_float(hi & 0xFFFF0000u);
    asm("cvt.rn.bf16x2.f32 %0, %1, %2;" : "=r"(lopack) : "f"(br), "f"(ar));
    return hi;
}

__device__ __forceinline__ float ex2f(float x) {
    float r;
    asm("ex2.approx.f32 %0, %1;" : "=f"(r) : "f"(x));
    return r;
}

// m16n8k16 row.col bf16 MMA, fp32 accumulate in place
__device__ __forceinline__ void mma_bf16(float c[4], const uint32_t a[4],
                                         uint32_t b0, uint32_t b1) {
    asm volatile(
        "mma.sync.aligned.m16n8k16.row.col.f32.bf16.bf16.f32 "
        "{%0,%1,%2,%3}, {%4,%5,%6,%7}, {%8,%9}, {%0,%1,%2,%3};\n"
        : "+f"(c[0]), "+f"(c[1]), "+f"(c[2]), "+f"(c[3])
        : "r"(a[0]), "r"(a[1]), "r"(a[2]), "r"(a[3]), "r"(b0), "r"(b1));
}

__device__ __forceinline__ void ldm_x4(uint32_t r[4], uint32_t addr) {
    asm volatile("ldmatrix.sync.aligned.m8n8.x4.shared.b16 {%0,%1,%2,%3}, [%4];"
                 : "=r"(r[0]), "=r"(r[1]), "=r"(r[2]), "=r"(r[3]) : "r"(addr));
}
__device__ __forceinline__ void ldm_x4_t(uint32_t r[4], uint32_t addr) {
    asm volatile("ldmatrix.sync.aligned.m8n8.x4.trans.shared.b16 {%0,%1,%2,%3}, [%4];"
                 : "=r"(r[0]), "=r"(r[1]), "=r"(r[2]), "=r"(r[3]) : "r"(addr));
}

// ===========================================================================
// Projection GEMM via mma.sync, split-bf16 (hh + lh + hl).
// CTA = 128M x 128N, K-loop 8 x 32. Warps: 4(M) x 2(N); warp = 32M x 64N.
// Q output pre-scaled by 0.25*log2(e).
// ===========================================================================
constexpr int RW = 20;  // u32 per 32-bf16 row (80 B)
constexpr float QSCALE = 0.3606737602222409f;  // 0.25 * log2(e)

__global__ __launch_bounds__(256, 2) void proj_mma(
    const float* __restrict__ Qin, const float* __restrict__ Kin, const float* __restrict__ Vin,
    const float* __restrict__ WQ,  const float* __restrict__ WK,  const float* __restrict__ WV,
    const float* __restrict__ bQ,  const float* __restrict__ bK,  const float* __restrict__ bV)
{
    __shared__ __align__(16) uint32_t Ah[128 * RW], Al[128 * RW];
    __shared__ __align__(16) uint32_t Wh[128 * RW], Wl[128 * RW];

    const float* A; const float* W; const float* bias; float scale;
    __nv_bfloat16 *Ch, *Cl;
    if (blockIdx.z == 0)      { A = Qin; W = WQ; bias = bQ; Ch = g_qh; Cl = g_ql; scale = QSCALE; }
    else if (blockIdx.z == 1) { A = Kin; W = WK; bias = bK; Ch = g_kh; Cl = g_kl; scale = 1.0f; }
    else                      { A = Vin; W = WV; bias = bV; Ch = g_vh; Cl = g_vl; scale = 1.0f; }

    const int tid = threadIdx.x;
    const int wid = tid >> 5, lane = tid & 31;
    const int warpM = wid >> 1, warpN = wid & 1;
    const int row0 = blockIdx.y * 128;
    const int col0 = blockIdx.x * 128;

    const uint32_t okA = (uint32_t)(warpM * 32 + (lane & 15)) * 80 + ((lane >> 4) << 4);
    const uint32_t okB = (uint32_t)(warpN * 64 + (lane & 7) + ((lane >> 4) << 3)) * 80
                       + (((lane >> 3) & 1) << 4);
    const uint32_t sAh = smem_u32(Ah) + okA, sAl = smem_u32(Al) + okA;
    const uint32_t sWh = smem_u32(Wh) + okB, sWl = smem_u32(Wl) + okB;

    const int lr = tid >> 1, sg = (tid & 1) * 16;

    float acc[2][8][4];
    #pragma unroll
    for (int m = 0; m < 2; m++)
        #pragma unroll
        for (int nt = 0; nt < 8; nt++)
            #pragma unroll
            for (int j = 0; j < 4; j++) acc[m][nt][j] = 0.0f;

    for (int it = 0; it < 8; it++) {
        if (it) __syncthreads();
        {
            const float* srcA = A + (size_t)(row0 + lr) * DM + it * 32 + sg;
            const float* srcW = W + (size_t)(col0 + lr) * DM + it * 32 + sg;
            uint4 h0, h1, l0, l1;
            float4 f0 = *reinterpret_cast<const float4*>(srcA);
            float4 f1 = *reinterpret_cast<const float4*>(srcA + 4);
            float4 f2 = *reinterpret_cast<const float4*>(srcA + 8);
            float4 f3 = *reinterpret_cast<const float4*>(srcA + 12);
            h0.x = bfsplit_pack(f0.x, f0.y, l0.x); h0.y = bfsplit_pack(f0.z, f0.w, l0.y);
            h0.z = bfsplit_pack(f1.x, f1.y, l0.z); h0.w = bfsplit_pack(f1.z, f1.w, l0.w);
            h1.x = bfsplit_pack(f2.x, f2.y, l1.x); h1.y = bfsplit_pack(f2.z, f2.w, l1.y);
            h1.z = bfsplit_pack(f3.x, f3.y, l1.z); h1.w = bfsplit_pack(f3.z, f3.w, l1.w);
            const int so = lr * RW + sg / 2;
            *reinterpret_cast<uint4*>(&Ah[so]) = h0; *reinterpret_cast<uint4*>(&Ah[so + 4]) = h1;
            *reinterpret_cast<uint4*>(&Al[so]) = l0; *reinterpret_cast<uint4*>(&Al[so + 4]) = l1;

            f0 = *reinterpret_cast<const float4*>(srcW);
            f1 = *reinterpret_cast<const float4*>(srcW + 4);
            f2 = *reinterpret_cast<const float4*>(srcW + 8);
            f3 = *reinterpret_cast<const float4*>(srcW + 12);
            h0.x = bfsplit_pack(f0.x, f0.y, l0.x); h0.y = bfsplit_pack(f0.z, f0.w, l0.y);
            h0.z = bfsplit_pack(f1.x, f1.y, l0.z); h0.w = bfsplit_pack(f1.z, f1.w, l0.w);
            h1.x = bfsplit_pack(f2.x, f2.y, l1.x); h1.y = bfsplit_pack(f2.z, f2.w, l1.y);
            h1.z = bfsplit_pack(f3.x, f3.y, l1.z); h1.w = bfsplit_pack(f3.z, f3.w, l1.w);
            *reinterpret_cast<uint4*>(&Wh[so]) = h0; *reinterpret_cast<uint4*>(&Wh[so + 4]) = h1;
            *reinterpret_cast<uint4*>(&Wl[so]) = l0; *reinterpret_cast<uint4*>(&Wl[so + 4]) = l1;
        }
        __syncthreads();

        #pragma unroll
        for (int ks = 0; ks < 2; ks++) {
            uint32_t aah[2][4], aal[2][4];
            ldm_x4(aah[0], sAh + ks * 32);
            ldm_x4(aal[0], sAl + ks * 32);
            ldm_x4(aah[1], sAh + 16 * 80 + ks * 32);
            ldm_x4(aal[1], sAl + 16 * 80 + ks * 32);

            #pragma unroll
            for (int np = 0; np < 4; np++) {
                uint32_t bh[4], bl[4];
                ldm_x4(bh, sWh + np * 16 * 80 + ks * 32);
                ldm_x4(bl, sWl + np * 16 * 80 + ks * 32);
                #pragma unroll
                for (int m = 0; m < 2; m++) {
                    mma_bf16(acc[m][2 * np],     aah[m], bh[0], bh[1]);
                    mma_bf16(acc[m][2 * np],     aal[m], bh[0], bh[1]);
                    mma_bf16(acc[m][2 * np],     aah[m], bl[0], bl[1]);
                    mma_bf16(acc[m][2 * np + 1], aah[m], bh[2], bh[3]);
                    mma_bf16(acc[m][2 * np + 1], aal[m], bh[2], bh[3]);
                    mma_bf16(acc[m][2 * np + 1], aah[m], bl[2], bl[3]);
                }
            }
        }
    }

    const int tq = lane & 3, g8 = lane >> 2;
    #pragma unroll
    for (int m = 0; m < 2; m++) {
        const size_t r0 = (size_t)(row0 + warpM * 32 + m * 16 + g8);
        #pragma unroll
        for (int nt = 0; nt < 8; nt++) {
            const int c = col0 + warpN * 64 + nt * 8 + 2 * tq;
            const float b0 = bias[c], b1 = bias[c + 1];
            uint32_t lo0, lo1;
            uint32_t hi0 = bfsplit_pack((acc[m][nt][0] + b0) * scale, (acc[m][nt][1] + b1) * scale, lo0);
            uint32_t hi1 = bfsplit_pack((acc[m][nt][2] + b0) * scale, (acc[m][nt][3] + b1) * scale, lo1);
            *reinterpret_cast<uint32_t*>(Ch + r0 * DM + c) = hi0;
            *reinterpret_cast<uint32_t*>(Cl + r0 * DM + c) = lo0;
            *reinterpret_cast<uint32_t*>(Ch + (r0 + 8) * DM + c) = hi1;
            *reinterpret_cast<uint32_t*>(Cl + (r0 + 8) * DM + c) = lo1;
        }
    }
}

// ===========================================================================
// Attention: 4 warps x 32 q-rows (halves K/V ldmatrix redundancy vs 8 warps).
// CTA = (q-tile 128, head, batch), 128 threads. p = ex2(score)*mask.
// ===========================================================================
constexpr int ROWU = 12;   // u32 stride per 16-bf16 row (48 B)

__global__ __launch_bounds__(128, 4) void attn_mma(const float* __restrict__ mask,
                                                   float* __restrict__ out)
{
    __shared__ __align__(16) uint32_t Qh[128 * ROWU], Ql[128 * ROWU];
    __shared__ __align__(16) uint32_t Kh[128 * ROWU], Kl[128 * ROWU];
    __shared__ __align__(16) uint32_t Vh[128 * ROWU], Vl[128 * ROWU];
    __shared__ float ms[128];

    const int tid = threadIdx.x;
    const int wid = tid >> 5, lane = tid & 31;
    const int t = lane & 3;
    const int q0 = blockIdx.x * 128;
    const int h = blockIdx.y;
    const int b = blockIdx.z;

    const uint32_t* gqh = reinterpret_cast<const uint32_t*>(g_qh);
    const uint32_t* gql = reinterpret_cast<const uint32_t*>(g_ql);
    const uint32_t* gkh = reinterpret_cast<const uint32_t*>(g_kh);
    const uint32_t* gkl = reinterpret_cast<const uint32_t*>(g_kl);
    const uint32_t* gvh = reinterpret_cast<const uint32_t*>(g_vh);
    const uint32_t* gvl = reinterpret_cast<const uint32_t*>(g_vl);

    const uint32_t okk = ((lane & 7) + ((lane >> 4) << 3)) * 48 + (((lane >> 3) & 1) << 4);
    const uint32_t okv = ((lane & 7) + (((lane >> 3) & 1) << 3)) * 48 + ((lane >> 4) << 4);
    const uint32_t okq0 = (wid * 32 + (lane & 7) + (((lane >> 3) & 1) << 3)) * 48 + ((lane >> 4) << 4);

    const uint32_t sKh = smem_u32(Kh) + okk, sKl = smem_u32(Kl) + okk;
    const uint32_t sVh = smem_u32(Vh) + okv, sVl = smem_u32(Vl) + okv;

    // load Q tile [128 x 16] hi/lo
    #pragma unroll
    for (int i = tid; i < 512; i += 128) {
        const int r = i >> 2, u = (i & 3) * 2;
        const size_t gi = ((size_t)(b * Ss + q0 + r)) * 128 + h * 8 + u;
        *reinterpret_cast<uint2*>(&Qh[r * ROWU + u]) = *reinterpret_cast<const uint2*>(gqh + gi);
        *reinterpret_cast<uint2*>(&Ql[r * ROWU + u]) = *reinterpret_cast<const uint2*>(gql + gi);
    }
    __syncthreads();

    uint32_t qah[2][4], qal[2][4];
    ldm_x4(qah[0], smem_u32(Qh) + okq0);
    ldm_x4(qal[0], smem_u32(Ql) + okq0);
    ldm_x4(qah[1], smem_u32(Qh) + okq0 + 16 * 48);
    ldm_x4(qal[1], smem_u32(Ql) + okq0 + 16 * 48);

    float ctx[2][2][4];
    float den[2][2];
    #pragma unroll
    for (int m = 0; m < 2; m++) {
        den[m][0] = den[m][1] = 0.0f;
        #pragma unroll
        for (int nn = 0; nn < 2; nn++)
            #pragma unroll
            for (int j = 0; j < 4; j++) ctx[m][nn][j] = 0.0f;
    }

    for (int c = 0; c < 4; c++) {
        __syncthreads();

        #pragma unroll
        for (int i = tid; i < 512; i += 128) {
            const int r = i >> 2, u = (i & 3) * 2;
            const size_t gi = ((size_t)(b * Ss + c * 128 + r)) * 128 + h * 8 + u;
            *reinterpret_cast<uint2*>(&Kh[r * ROWU + u]) = *reinterpret_cast<const uint2*>(gkh + gi);
            *reinterpret_cast<uint2*>(&Kl[r * ROWU + u]) = *reinterpret_cast<const uint2*>(gkl + gi);
            *reinterpret_cast<uint2*>(&Vh[r * ROWU + u]) = *reinterpret_cast<const uint2*>(gvh + gi);
            *reinterpret_cast<uint2*>(&Vl[r * ROWU + u]) = *reinterpret_cast<const uint2*>(gvl + gi);
        }
        if (tid < 128) ms[tid] = mask[b * Ss + c * 128 + tid];
        __syncthreads();

        #pragma unroll
        for (int kt = 0; kt < 8; kt++) {
            // ---- QK^T for 16 keys, both m-tiles ----
            uint32_t bh[4], bl[4];
            ldm_x4(bh, sKh + kt * 768);
            ldm_x4(bl, sKl + kt * 768);

            float sc[2][2][4];
            #pragma unroll
            for (int m = 0; m < 2; m++) {
                #pragma unroll
                for (int nn = 0; nn < 2; nn++)
                    #pragma unroll
                    for (int j = 0; j < 4; j++) sc[m][nn][j] = 0.0f;
                mma_bf16(sc[m][0], qah[m], bh[0], bh[1]);
                mma_bf16(sc[m][0], qah[m], bl[0], bl[1]);
                mma_bf16(sc[m][0], qal[m], bh[0], bh[1]);
                mma_bf16(sc[m][1], qah[m], bh[2], bh[3]);
                mma_bf16(sc[m][1], qah[m], bl[2], bl[3]);
                mma_bf16(sc[m][1], qal[m], bh[2], bh[3]);
            }

            // ---- epilogue: p = ex2(score)*mask (score pre-scaled) ----
            const float m0 = ms[kt * 16 + 2 * t];
            const float m1 = ms[kt * 16 + 2 * t + 1];
            const float m2 = ms[kt * 16 + 8 + 2 * t];
            const float m3 = ms[kt * 16 + 8 + 2 * t + 1];

            uint32_t pah[2][4], pal[2][4];
            #pragma unroll
            for (int m = 0; m < 2; m++) {
                const float p00 = ex2f(sc[m][0][0]) * m0;
                const float p01 = ex2f(sc[m][0][1]) * m1;
                const float p02 = ex2f(sc[m][0][2]) * m0;
                const float p03 = ex2f(sc[m][0][3]) * m1;
                const float p10 = ex2f(sc[m][1][0]) * m2;
                const float p11 = ex2f(sc[m][1][1]) * m3;
                const float p12 = ex2f(sc[m][1][2]) * m2;
                const float p13 = ex2f(sc[m][1][3]) * m3;
                den[m][0] += p00 + p01 + p10 + p11;
                den[m][1] += p02 + p03 + p12 + p13;
                pah[m][0] = bfsplit_pack(p00, p01, pal[m][0]);
                pah[m][1] = bfsplit_pack(p02, p03, pal[m][1]);
                pah[m][2] = bfsplit_pack(p10, p11, pal[m][2]);
                pah[m][3] = bfsplit_pack(p12, p13, pal[m][3]);
            }

            // ---- P.V for these 16 keys ----
            uint32_t vh[4], vl[4];
            ldm_x4_t(vh, sVh + kt * 768);
            ldm_x4_t(vl, sVl + kt * 768);
            #pragma unroll
            for (int m = 0; m < 2; m++) {
                mma_bf16(ctx[m][0], pah[m], vh[0], vh[1]);
                mma_bf16(ctx[m][0], pah[m], vl[0], vl[1]);
                mma_bf16(ctx[m][0], pal[m], vh[0], vh[1]);
                mma_bf16(ctx[m][1], pah[m], vh[2], vh[3]);
                mma_bf16(ctx[m][1], pah[m], vl[2], vl[3]);
                mma_bf16(ctx[m][1], pal[m], vh[2], vh[3]);
            }
        }
    }

    const int g = lane >> 2;
    #pragma unroll
    for (int m = 0; m < 2; m++) {
        float d0 = den[m][0], d1 = den[m][1];
        d0 += __shfl_xor_sync(0xFFFFFFFFu, d0, 1);
        d0 += __shfl_xor_sync(0xFFFFFFFFu, d0, 2);
        d1 += __shfl_xor_sync(0xFFFFFFFFu, d1, 1);
        d1 += __shfl_xor_sync(0xFFFFFFFFu, d1, 2);
        const float i0 = 1.0f / (d0 + 1e-8f);
        const float i1 = 1.0f / (d1 + 1e-8f);

        const size_t row0 = (size_t)(b * Ss + q0 + wid * 32 + m * 16 + g);
        float2 o00 = make_float2(ctx[m][0][0] * i0, ctx[m][0][1] * i0);
        float2 o01 = make_float2(ctx[m][0][2] * i1, ctx[m][0][3] * i1);
        float2 o10 = make_float2(ctx[m][1][0] * i0, ctx[m][1][1] * i0);
        float2 o11 = make_float2(ctx[m][1][2] * i1, ctx[m][1][3] * i1);
        *reinterpret_cast<float2*>(out + row0 * DM + h * DH + 2 * t) = o00;
        *reinterpret_cast<float2*>(out + (row0 + 8) * DM + h * DH + 2 * t) = o01;
        *reinterpret_cast<float2*>(out + row0 * DM + h * DH + 8 + 2 * t) = o10;
        *reinterpret_cast<float2*>(out + (row0 + 8) * DM + h * DH + 8 + 2 * t) = o11;
    }
}

// ===========================================================================
extern "C" void kernel_launch(void* const* d_in, const int* in_sizes, int n_in,
                              void* d_out, int out_size)
{
    const float* Q    = (const float*)d_in[0];
    const float* K    = (const float*)d_in[1];
    const float* V    = (const float*)d_in[2];
    const float* mask = (const float*)d_in[3];
    const float* W_Q  = (const float*)d_in[4];
    const float* b_Q  = (const float*)d_in[5];
    const float* W_K  = (const float*)d_in[6];
    const float* b_K  = (const float*)d_in[7];
    const float* W_V  = (const float*)d_in[8];
    const float* b_V  = (const float*)d_in[9];
    float* out = (float*)d_out;

    dim3 gridP(2, Mrows / 128, 3);
    proj_mma<<<gridP, 256>>>(Q, K, V, W_Q, W_K, W_V, b_Q, b_K, b_V);

    dim3 gridA(4, NH, Bb);
    attn_mma<<<gridA, 128>>>(mask, out);
}